// round 7
// baseline (speedup 1.0000x reference)
#include <cuda_runtime.h>

#define N_NEURON 500000
#define N_EDGE   10000000
#define NVEC     (N_NEURON / 4)                       // 125000 float4 chunks
#define TPB      256
#define EPT      4                                    // edges per thread
#define EDGE_THREADS (N_EDGE / EPT)                   // 2,500,000
#define EDGE_BLOCKS  ((EDGE_THREADS + TPB - 1) / TPB) // 9766
#define NEURON_BLOCKS ((NVEC + TPB - 1) / TPB)        // 489

// dual-exponential constants (match reference exactly)
#define DT_C     0.1f
#define LAMDA_D  (0.1f / 2.0f)    // DT/TAO_D
#define LAMDA_R  (0.1f / 10.0f)   // DT/TAO_R
#define INV_TAO_D 0.5f            // 1/TAO_D

// scratch (no cudaMalloc allowed)
__device__ float        g_rnew[N_NEURON];
__device__ unsigned int g_done;   // neuron-block completion counter

// tiny reset: zero the gate counter at the start of every replay
__global__ void reset_kernel() { g_done = 0u; }

// ---------------------------------------------------------------------------
// Fused kernel.
//  Phase 1 (blocks 0..488): float4 neuron update -> g_rnew, out=Ieff; publish
//          via __threadfence + release-style atomicAdd on g_done.
//  Phase 2 (all blocks): issue edge STREAMING loads (post/pre/w) BEFORE the
//          gate so the 120 MB of coalesced traffic overlaps the neuron phase.
//  Gate:   spin (acquire load + nanosleep) until all 489 neuron blocks done.
//  Phase 3: L2 gathers of g_rnew (plain coherent loads) + REDG atomics.
// Deadlock-safe: __launch_bounds__(256,6) -> >=888 resident blocks in the
// deterministic first wave, covering all 489 publisher blocks.
// ---------------------------------------------------------------------------
__global__ void __launch_bounds__(TPB, 6) fused_kernel(
    const int*    __restrict__ post,
    const int*    __restrict__ pre,
    const float*  __restrict__ w,
    const float4* __restrict__ Iback,
    const float4* __restrict__ spike,
    const float4* __restrict__ s,
    const float4* __restrict__ r,
    const float4* __restrict__ noise,
    const float*  __restrict__ dt_over_tau,
    const float*  __restrict__ sqrt_coeff,
    const float*  __restrict__ sig,
    const float*  __restrict__ mu,
    float*        __restrict__ out)
{
    const int bid = blockIdx.x;
    const int tid = threadIdx.x;

    // ---------------- phase 1: neuron update ----------------
    if (bid < NEURON_BLOCKS) {
        int i = bid * TPB + tid;
        if (i < NVEC) {
            float dtau  = __ldg(dt_over_tau);
            float scale = __ldg(sig) / __ldg(sqrt_coeff);
            float m     = __ldg(mu);

            float4 ib = Iback[i];
            float4 nz = noise[i];
            float4 sv = s[i];
            float4 sp = spike[i];
            float4 rv = r[i];

            float4 ieff, rn;
            {
                float ibn = ib.x + dtau * (nz.x - ib.x);
                ieff.x = ibn * scale + m;
                float sn = sv.x + LAMDA_R * (-sv.x + sp.x * INV_TAO_D);
                rn.x = rv.x - LAMDA_D * rv.x + DT_C * sn;
            }
            {
                float ibn = ib.y + dtau * (nz.y - ib.y);
                ieff.y = ibn * scale + m;
                float sn = sv.y + LAMDA_R * (-sv.y + sp.y * INV_TAO_D);
                rn.y = rv.y - LAMDA_D * rv.y + DT_C * sn;
            }
            {
                float ibn = ib.z + dtau * (nz.z - ib.z);
                ieff.z = ibn * scale + m;
                float sn = sv.z + LAMDA_R * (-sv.z + sp.z * INV_TAO_D);
                rn.z = rv.z - LAMDA_D * rv.z + DT_C * sn;
            }
            {
                float ibn = ib.w + dtau * (nz.w - ib.w);
                ieff.w = ibn * scale + m;
                float sn = sv.w + LAMDA_R * (-sv.w + sp.w * INV_TAO_D);
                rn.w = rv.w - LAMDA_D * rv.w + DT_C * sn;
            }

            reinterpret_cast<float4*>(g_rnew)[i] = rn;
            reinterpret_cast<float4*>(out)[i]    = ieff;  // seed accumulator
        }
        __syncthreads();
        if (tid == 0) {
            __threadfence();              // make g_rnew/out visible at L2
            atomicAdd(&g_done, 1u);       // publish
        }
    }

    // ---------------- phase 2: edge streaming loads (pre-gate) ----------------
    int t = bid * TPB + tid;
    int e = t * EPT;
    if (e >= N_EDGE) return;              // N_EDGE % 4 == 0, full quads only

    int4   p  = *reinterpret_cast<const int4*>(post + e);
    int4   q  = *reinterpret_cast<const int4*>(pre + e);
    float4 ww = *reinterpret_cast<const float4*>(w + e);

    // ---------------- gate: wait for all neuron blocks ----------------
    unsigned int v;
    for (;;) {
        asm volatile("ld.acquire.gpu.global.u32 %0, [%1];"
                     : "=r"(v) : "l"(&g_done) : "memory");
        if (v >= (unsigned)NEURON_BLOCKS) break;
        __nanosleep(64);
    }

    // ---------------- phase 3: gather + atomic scatter ----------------
    // plain coherent loads (NOT __ldg: .nc is illegal across the in-kernel
    // producer/consumer edge); g_rnew and out are L2-resident.
    float r0 = g_rnew[q.x];
    float r1 = g_rnew[q.y];
    float r2 = g_rnew[q.z];
    float r3 = g_rnew[q.w];

    atomicAdd(out + p.x, ww.x * r0);
    atomicAdd(out + p.y, ww.y * r1);
    atomicAdd(out + p.z, ww.z * r2);
    atomicAdd(out + p.w, ww.w * r3);
}

extern "C" void kernel_launch(void* const* d_in, const int* in_sizes, int n_in,
                              void* d_out, int out_size)
{
    const float* weight      = (const float*)d_in[0];
    const int*   edges       = (const int*)d_in[1];   // [2, N_EDGE] int32
    const float* Iback       = (const float*)d_in[2];
    const float* spike       = (const float*)d_in[3];
    const float* s           = (const float*)d_in[4];
    const float* r           = (const float*)d_in[5];
    const float* noise       = (const float*)d_in[6];
    const float* dt_over_tau = (const float*)d_in[7];
    const float* sqrt_coeff  = (const float*)d_in[8];
    const float* sig         = (const float*)d_in[9];
    const float* mu          = (const float*)d_in[10];
    float* out = (float*)d_out;

    const int* post = edges;
    const int* pre  = edges + N_EDGE;

    reset_kernel<<<1, 1>>>();
    fused_kernel<<<EDGE_BLOCKS, TPB>>>(
        post, pre, weight,
        (const float4*)Iback, (const float4*)spike, (const float4*)s,
        (const float4*)r, (const float4*)noise,
        dt_over_tau, sqrt_coeff, sig, mu, out);
}

// round 14
// speedup vs baseline: 1.1783x; 1.1783x over previous
#include <cuda_runtime.h>

#define N_NEURON 500000
#define N_EDGE   10000000
#define NVEC     (N_NEURON / 4)                       // 125000 float4 chunks
#define TPB      256
#define EPT      4                                    // edges per thread
#define EDGE_THREADS (N_EDGE / EPT)                   // 2,500,000
#define EDGE_BLOCKS  ((EDGE_THREADS + TPB - 1) / TPB) // 9766
#define NEURON_BLOCKS ((NVEC + TPB - 1) / TPB)        // 489

// dual-exponential constants (match reference exactly)
#define DT_C     0.1f
#define LAMDA_D  (0.1f / 2.0f)    // DT/TAO_D
#define LAMDA_R  (0.1f / 10.0f)   // DT/TAO_R
#define INV_TAO_D 0.5f            // 1/TAO_D

// scratch (no cudaMalloc allowed)
__device__ float        g_rnew[N_NEURON];
__device__ unsigned int g_done;   // neuron-block completion counter

// tiny reset: zero the gate counter at the start of every replay
__global__ void reset_kernel() { g_done = 0u; }

// ---------------------------------------------------------------------------
// Fused kernel, leader-only gate.
//  Phase 1 (blocks 0..488): float4 neuron update -> g_rnew, out=Ieff; publish
//          via __threadfence + atomicAdd on g_done.
//  Phase 2 (all blocks): issue edge STREAMING loads (post/pre/w) BEFORE the
//          gate so the 120 MB of coalesced traffic overlaps the neuron phase.
//  Gate:   tid==0 spins (acquire + nanosleep), block released by syncthreads.
//  Phase 3: L2 gathers of g_rnew (plain coherent loads) + REDG atomics.
// Deadlock-safe: __launch_bounds__(256,6) -> >=888 resident blocks in the
// deterministic first wave, covering all 489 publisher blocks.
// ---------------------------------------------------------------------------
__global__ void __launch_bounds__(TPB, 6) fused_kernel(
    const int*    __restrict__ post,
    const int*    __restrict__ pre,
    const float*  __restrict__ w,
    const float4* __restrict__ Iback,
    const float4* __restrict__ spike,
    const float4* __restrict__ s,
    const float4* __restrict__ r,
    const float4* __restrict__ noise,
    const float*  __restrict__ dt_over_tau,
    const float*  __restrict__ sqrt_coeff,
    const float*  __restrict__ sig,
    const float*  __restrict__ mu,
    float*        __restrict__ out)
{
    const int bid = blockIdx.x;
    const int tid = threadIdx.x;

    // ---------------- phase 1: neuron update ----------------
    if (bid < NEURON_BLOCKS) {
        int i = bid * TPB + tid;
        if (i < NVEC) {
            float dtau  = __ldg(dt_over_tau);
            float scale = __ldg(sig) / __ldg(sqrt_coeff);
            float m     = __ldg(mu);

            float4 ib = Iback[i];
            float4 nz = noise[i];
            float4 sv = s[i];
            float4 sp = spike[i];
            float4 rv = r[i];

            float4 ieff, rn;
            {
                float ibn = ib.x + dtau * (nz.x - ib.x);
                ieff.x = ibn * scale + m;
                float sn = sv.x + LAMDA_R * (-sv.x + sp.x * INV_TAO_D);
                rn.x = rv.x - LAMDA_D * rv.x + DT_C * sn;
            }
            {
                float ibn = ib.y + dtau * (nz.y - ib.y);
                ieff.y = ibn * scale + m;
                float sn = sv.y + LAMDA_R * (-sv.y + sp.y * INV_TAO_D);
                rn.y = rv.y - LAMDA_D * rv.y + DT_C * sn;
            }
            {
                float ibn = ib.z + dtau * (nz.z - ib.z);
                ieff.z = ibn * scale + m;
                float sn = sv.z + LAMDA_R * (-sv.z + sp.z * INV_TAO_D);
                rn.z = rv.z - LAMDA_D * rv.z + DT_C * sn;
            }
            {
                float ibn = ib.w + dtau * (nz.w - ib.w);
                ieff.w = ibn * scale + m;
                float sn = sv.w + LAMDA_R * (-sv.w + sp.w * INV_TAO_D);
                rn.w = rv.w - LAMDA_D * rv.w + DT_C * sn;
            }

            reinterpret_cast<float4*>(g_rnew)[i] = rn;
            reinterpret_cast<float4*>(out)[i]    = ieff;  // seed accumulator
        }
        __syncthreads();
        if (tid == 0) {
            __threadfence();              // make g_rnew/out visible at L2
            atomicAdd(&g_done, 1u);       // publish
        }
    }

    // ---------------- phase 2: edge streaming loads (pre-gate) ----------------
    int t = bid * TPB + tid;
    int e = t * EPT;
    bool active = (e < N_EDGE);           // N_EDGE % 4 == 0, full quads only

    int4   p  = {0, 0, 0, 0};
    int4   q  = {0, 0, 0, 0};
    float4 ww = {0.f, 0.f, 0.f, 0.f};
    if (active) {
        p  = *reinterpret_cast<const int4*>(post + e);
        q  = *reinterpret_cast<const int4*>(pre + e);
        ww = *reinterpret_cast<const float4*>(w + e);
    }

    // ---------------- gate: leader spins, block follows ----------------
    if (tid == 0) {
        unsigned int v;
        for (;;) {
            asm volatile("ld.acquire.gpu.global.u32 %0, [%1];"
                         : "=r"(v) : "l"(&g_done) : "memory");
            if (v >= (unsigned)NEURON_BLOCKS) break;
            __nanosleep(256);
        }
    }
    __syncthreads();                      // block-wide release

    if (!active) return;

    // ---------------- phase 3: gather + atomic scatter ----------------
    // plain coherent loads (NOT __ldg: .nc is unsafe across the in-kernel
    // producer/consumer edge); g_rnew and out are L2-resident.
    float r0 = g_rnew[q.x];
    float r1 = g_rnew[q.y];
    float r2 = g_rnew[q.z];
    float r3 = g_rnew[q.w];

    atomicAdd(out + p.x, ww.x * r0);
    atomicAdd(out + p.y, ww.y * r1);
    atomicAdd(out + p.z, ww.z * r2);
    atomicAdd(out + p.w, ww.w * r3);
}

extern "C" void kernel_launch(void* const* d_in, const int* in_sizes, int n_in,
                              void* d_out, int out_size)
{
    const float* weight      = (const float*)d_in[0];
    const int*   edges       = (const int*)d_in[1];   // [2, N_EDGE] int32
    const float* Iback       = (const float*)d_in[2];
    const float* spike       = (const float*)d_in[3];
    const float* s           = (const float*)d_in[4];
    const float* r           = (const float*)d_in[5];
    const float* noise       = (const float*)d_in[6];
    const float* dt_over_tau = (const float*)d_in[7];
    const float* sqrt_coeff  = (const float*)d_in[8];
    const float* sig         = (const float*)d_in[9];
    const float* mu          = (const float*)d_in[10];
    float* out = (float*)d_out;

    const int* post = edges;
    const int* pre  = edges + N_EDGE;

    reset_kernel<<<1, 1>>>();
    fused_kernel<<<EDGE_BLOCKS, TPB>>>(
        post, pre, weight,
        (const float4*)Iback, (const float4*)spike, (const float4*)s,
        (const float4*)r, (const float4*)noise,
        dt_over_tau, sqrt_coeff, sig, mu, out);
}

// round 17
// speedup vs baseline: 1.2211x; 1.0364x over previous
#include <cuda_runtime.h>

#define N_NEURON 500000
#define N_EDGE   10000000

// dual-exponential constants (match reference exactly)
#define DT_C     0.1f
#define LAMDA_D  (0.1f / 2.0f)    // DT/TAO_D
#define LAMDA_R  (0.1f / 10.0f)   // DT/TAO_R
#define INV_TAO_D 0.5f            // 1/TAO_D

// scratch: r_new lives here between the two kernels (no cudaMalloc allowed)
__device__ float g_rnew[N_NEURON];

// ---------------------------------------------------------------------------
// Kernel A: per-neuron fused update, float4-vectorized (N_NEURON % 4 == 0).
//   Iback_new = Iback + dt_over_tau*(noise - Iback)
//   Ieff      = Iback_new / sqrt_coeff * sig + mu
//   s_new     = s + LAMDA_R*(-s + spike/TAO_D)
//   r_new     = r - LAMDA_D*r + DT*s_new
// Writes r_new to scratch, seeds out = Ieff (accumulator base).
// ---------------------------------------------------------------------------
__global__ void neuron_kernel(const float4* __restrict__ Iback,
                              const float4* __restrict__ spike,
                              const float4* __restrict__ s,
                              const float4* __restrict__ r,
                              const float4* __restrict__ noise,
                              const float* __restrict__ dt_over_tau,
                              const float* __restrict__ sqrt_coeff,
                              const float* __restrict__ sig,
                              const float* __restrict__ mu,
                              float4* __restrict__ out)
{
    int i = blockIdx.x * blockDim.x + threadIdx.x;
    if (i >= N_NEURON / 4) return;

    float dtau  = __ldg(dt_over_tau);
    float scale = __ldg(sig) / __ldg(sqrt_coeff);
    float m     = __ldg(mu);

    float4 ib = Iback[i];
    float4 nz = noise[i];
    float4 sv = s[i];
    float4 sp = spike[i];
    float4 rv = r[i];

    float4 ieff, rn;
    {
        float ibn = ib.x + dtau * (nz.x - ib.x);
        ieff.x = ibn * scale + m;
        float sn = sv.x + LAMDA_R * (-sv.x + sp.x * INV_TAO_D);
        rn.x = rv.x - LAMDA_D * rv.x + DT_C * sn;
    }
    {
        float ibn = ib.y + dtau * (nz.y - ib.y);
        ieff.y = ibn * scale + m;
        float sn = sv.y + LAMDA_R * (-sv.y + sp.y * INV_TAO_D);
        rn.y = rv.y - LAMDA_D * rv.y + DT_C * sn;
    }
    {
        float ibn = ib.z + dtau * (nz.z - ib.z);
        ieff.z = ibn * scale + m;
        float sn = sv.z + LAMDA_R * (-sv.z + sp.z * INV_TAO_D);
        rn.z = rv.z - LAMDA_D * rv.z + DT_C * sn;
    }
    {
        float ibn = ib.w + dtau * (nz.w - ib.w);
        ieff.w = ibn * scale + m;
        float sn = sv.w + LAMDA_R * (-sv.w + sp.w * INV_TAO_D);
        rn.w = rv.w - LAMDA_D * rv.w + DT_C * sn;
    }

    reinterpret_cast<float4*>(g_rnew)[i] = rn;
    out[i] = ieff;   // accumulator base (out is poisoned by harness)
}

// ---------------------------------------------------------------------------
// Kernel B: COO edge scatter, 2 edges per thread (best measured total:
// 85.06us; edge phase pinned at LTS-traffic floor ~77us, L2 ~90%).
//   out[post_e] += w_e * r_new[pre_e]
// edges are INT32 on device: post = edges[0:N_EDGE], pre = edges[N_EDGE:2N].
// Gathers issued before atomics; r_new (2 MB) and out (2 MB) are
// L2-resident; atomics compile to REDG.
// ---------------------------------------------------------------------------
__global__ void __launch_bounds__(256) edge_kernel(
                            const int* __restrict__ post,
                            const int* __restrict__ pre,
                            const float* __restrict__ w,
                            float* __restrict__ out)
{
    int t = blockIdx.x * blockDim.x + threadIdx.x;
    int i = t * 2;
    if (i >= N_EDGE) return;   // N_EDGE % 2 == 0, full pairs only

    int2   p  = *reinterpret_cast<const int2*>(post + i);
    int2   q  = *reinterpret_cast<const int2*>(pre + i);
    float2 ww = *reinterpret_cast<const float2*>(w + i);

    // gather first (overlap the two random loads), then scatter
    float r0 = __ldg(&g_rnew[q.x]);
    float r1 = __ldg(&g_rnew[q.y]);

    atomicAdd(out + p.x, ww.x * r0);
    atomicAdd(out + p.y, ww.y * r1);
}

extern "C" void kernel_launch(void* const* d_in, const int* in_sizes, int n_in,
                              void* d_out, int out_size)
{
    const float* weight      = (const float*)d_in[0];
    const int*   edges       = (const int*)d_in[1];   // [2, N_EDGE] int32
    const float* Iback       = (const float*)d_in[2];
    const float* spike       = (const float*)d_in[3];
    const float* s           = (const float*)d_in[4];
    const float* r           = (const float*)d_in[5];
    const float* noise       = (const float*)d_in[6];
    const float* dt_over_tau = (const float*)d_in[7];
    const float* sqrt_coeff  = (const float*)d_in[8];
    const float* sig         = (const float*)d_in[9];
    const float* mu          = (const float*)d_in[10];
    float* out = (float*)d_out;

    const int* post = edges;
    const int* pre  = edges + N_EDGE;

    int threads = 256;
    int nvec = N_NEURON / 4;
    int nblocks = (nvec + threads - 1) / threads;
    neuron_kernel<<<nblocks, threads>>>(
        (const float4*)Iback, (const float4*)spike, (const float4*)s,
        (const float4*)r, (const float4*)noise,
        dt_over_tau, sqrt_coeff, sig, mu, (float4*)out);

    int nthreads_edge = N_EDGE / 2;
    int eblocks = (nthreads_edge + threads - 1) / threads;
    edge_kernel<<<eblocks, threads>>>(post, pre, weight, out);
}